// round 9
// baseline (speedup 1.0000x reference)
#include <cuda_runtime.h>

#define BATCH 4096
#define TT    512
#define IN    20
#define HID   51
#define NG    204
#define KDIM  71              // HID + IN
#define WROW  204             // interleaved weight row: [u*4+g], u<51
#define SPB   16
#define NBLK  (BATCH / SPB)   // 256
#define NTHR  128

// float offsets in dynamic smem
#define OFF_W   0                       // w_il[71][204]
#define OFF_HX  (KDIM * WROW)           // two dup buffers [2][71][32]; rows 0..50 h, 51..70 x
#define HXBUF   (KDIM * 32)             // 2272 floats per buffer
#define OFF_W2  (OFF_HX + 2 * HXBUF)    // W_ih2 [4][51]
#define SMEM_FLOATS (OFF_W2 + NG)
#define SMEM_BYTES  (SMEM_FLOATS * 4)   // ~77 KB -> 2 CTAs/SM

typedef unsigned long long ull;

__device__ __forceinline__ ull pack2(float v) {
    ull r; asm("mov.b64 %0, {%1, %1};" : "=l"(r) : "f"(v)); return r;
}
__device__ __forceinline__ ull pack2x(float lo, float hi) {
    ull r; asm("mov.b64 %0, {%1, %2};" : "=l"(r) : "f"(lo), "f"(hi)); return r;
}
__device__ __forceinline__ ull fma2(ull a, ull b, ull c) {
    ull d; asm("fma.rn.f32x2 %0, %1, %2, %3;" : "=l"(d) : "l"(a), "l"(b), "l"(c)); return d;
}
__device__ __forceinline__ void unpack2(ull v, float& lo, float& hi) {
    asm("mov.b64 {%0, %1}, %2;" : "=f"(lo), "=f"(hi) : "l"(v));
}
__device__ __forceinline__ float fsig(float x)  { return __fdividef(1.0f, 1.0f + __expf(-x)); }
__device__ __forceinline__ float ftanh_(float x){ return 1.0f - __fdividef(2.0f, __expf(2.0f * x) + 1.0f); }

__global__ __launch_bounds__(NTHR, 2) void lstm_v9_kernel(
    const float* __restrict__ x,
    const float* __restrict__ W_ih1, const float* __restrict__ W_hh1,
    const float* __restrict__ b_ih1, const float* __restrict__ b_hh1,
    const float* __restrict__ W_ih2, const float* __restrict__ W_hh2,
    const float* __restrict__ b_ih2, const float* __restrict__ b_hh2,
    const float* __restrict__ W_mu,  const float* __restrict__ b_mu,
    const float* __restrict__ W_lv,  const float* __restrict__ b_lv,
    float* __restrict__ out)
{
    extern __shared__ float sm[];
    const int tid  = threadIdx.x;
    const int lane = tid & 31;
    const int b16  = blockIdx.x * SPB;

    // ---------------- init ----------------
    // interleaved: w_il[k][u*4+g], gate g: 0=i,1=f,2=g,3=o ; source row G = g*51+u
    for (int i = tid; i < KDIM * WROW; i += NTHR) {
        int k = i / WROW, j = i % WROW;
        int u = j >> 2, g = j & 3;
        int G = g * HID + u;
        sm[OFF_W + i] = (k < HID) ? W_hh1[G * HID + k] : W_ih1[G * IN + (k - HID)];
    }
    for (int i = tid; i < HID * 32; i += NTHR) sm[OFF_HX + i] = 0.f;  // h rows of buf0 (dup)
    for (int i = tid; i < NG; i += NTHR) sm[OFF_W2 + i] = W_ih2[i];   // [4][51]
    for (int i = tid; i < SPB * IN; i += NTHR) {                      // x(0) dup -> buf0 rows 51..70
        int s = i / IN, j = i % IN;
        float v = x[((size_t)(b16 + s) * TT) * IN + j];
        sm[OFF_HX + (HID + j) * 32 + 2 * s]     = v;
        sm[OFF_HX + (HID + j) * 32 + 2 * s + 1] = v;
    }

    // ---- thread roles ----
    const bool is_main = (tid < 96);          // warps 0..2: u = tid>>1 (0..47), 8 seqs
    const int  um  = tid >> 1;
    const int  sh8 = (tid & 1) << 3;
    // warp 3, lanes 0..23: remainder units 48..50, gate-pair p, seq-quad q
    const bool is_w3m = (tid >= 96 && lane < 24);
    const int  u3 = 48 + (lane >> 3);
    const int  p3 = (lane >> 2) & 1;
    const int  q3 = lane & 3;
    // warp 3, lanes 0..15 also do layer 2 (seq = lane); lanes 24..31 do x prefetch (2 seqs each)
    const bool is_l2 = (tid >= 96 && lane < 16);
    const bool is_xp = (tid >= 96 && lane >= 24);
    const int  xs0 = (lane - 24) * 2;

    ull bif = 0ULL, bgo = 0ULL, b3 = 0ULL;
    if (is_main) {
        bif = pack2x(b_ih1[um] + b_hh1[um],             b_ih1[HID + um]   + b_hh1[HID + um]);
        bgo = pack2x(b_ih1[2*HID + um] + b_hh1[2*HID + um], b_ih1[3*HID + um] + b_hh1[3*HID + um]);
    }
    if (is_w3m) {
        int glo = p3 * 2, ghi = p3 * 2 + 1;
        b3 = pack2x(b_ih1[glo*HID + u3] + b_hh1[glo*HID + u3],
                    b_ih1[ghi*HID + u3] + b_hh1[ghi*HID + u3]);
    }
    float c1[8] = {0,0,0,0,0,0,0,0};   // main: 8 cells ; w3 if-lanes: use [0..3]

    float c2 = 0.f, h2 = 0.f, sum_h2 = 0.f;
    float l2b[4] = {0,0,0,0}, l2w[4] = {0,0,0,0};
    if (is_l2) {
        #pragma unroll
        for (int g = 0; g < 4; g++) { l2b[g] = b_ih2[g] + b_hh2[g]; l2w[g] = W_hh2[g]; }
    }
    __syncthreads();

    #pragma unroll 1
    for (int t = 0; t < TT; t++) {
        const float* A = &sm[OFF_HX + (t & 1) * HXBUF];
        float*       B = &sm[OFF_HX + ((t + 1) & 1) * HXBUF];

        if (is_main) {
            // ---- unit um, 8 seqs, gate-pairs in f32x2 lanes; 5 LDS + 16 FFMA2 per k, 0 MOV ----
            ull aif[8], ago[8];
            #pragma unroll
            for (int s = 0; s < 8; s++) { aif[s] = bif; ago[s] = bgo; }
            const float* wb = &sm[OFF_W + um * 4];
            const float* hb = A + sh8 * 2;
            #pragma unroll
            for (int k = 0; k < KDIM; k++) {
                ulonglong2 wp = *reinterpret_cast<const ulonglong2*>(wb + k * WROW); // {wi,wf},{wg,wo}
                const float* hr = hb + k * 32;
                ulonglong2 h0 = *reinterpret_cast<const ulonglong2*>(hr);
                ulonglong2 h1 = *reinterpret_cast<const ulonglong2*>(hr + 4);
                ulonglong2 h2v = *reinterpret_cast<const ulonglong2*>(hr + 8);
                ulonglong2 h3v = *reinterpret_cast<const ulonglong2*>(hr + 12);
                aif[0] = fma2(wp.x, h0.x, aif[0]);  ago[0] = fma2(wp.y, h0.x, ago[0]);
                aif[1] = fma2(wp.x, h0.y, aif[1]);  ago[1] = fma2(wp.y, h0.y, ago[1]);
                aif[2] = fma2(wp.x, h1.x, aif[2]);  ago[2] = fma2(wp.y, h1.x, ago[2]);
                aif[3] = fma2(wp.x, h1.y, aif[3]);  ago[3] = fma2(wp.y, h1.y, ago[3]);
                aif[4] = fma2(wp.x, h2v.x, aif[4]); ago[4] = fma2(wp.y, h2v.x, ago[4]);
                aif[5] = fma2(wp.x, h2v.y, aif[5]); ago[5] = fma2(wp.y, h2v.y, ago[5]);
                aif[6] = fma2(wp.x, h3v.x, aif[6]); ago[6] = fma2(wp.y, h3v.x, ago[6]);
                aif[7] = fma2(wp.x, h3v.y, aif[7]); ago[7] = fma2(wp.y, h3v.y, ago[7]);
            }
            // ---- in-register activations; write h dup to B ----
            ull hd[8];
            #pragma unroll
            for (int s = 0; s < 8; s++) {
                float gi, gf, gg, go;
                unpack2(aif[s], gi, gf);
                unpack2(ago[s], gg, go);
                float c = fsig(gf) * c1[s] + fsig(gi) * ftanh_(gg);
                c1[s] = c;
                hd[s] = pack2(fsig(go) * ftanh_(c));
            }
            float* Bo = B + um * 32 + sh8 * 2;
            *reinterpret_cast<ulonglong2*>(Bo)      = make_ulonglong2(hd[0], hd[1]);
            *reinterpret_cast<ulonglong2*>(Bo + 4)  = make_ulonglong2(hd[2], hd[3]);
            *reinterpret_cast<ulonglong2*>(Bo + 8)  = make_ulonglong2(hd[4], hd[5]);
            *reinterpret_cast<ulonglong2*>(Bo + 12) = make_ulonglong2(hd[6], hd[7]);
        } else {
            // -------- warp 3 --------
            float4 xv0[5], xv1[5];
            if (is_xp && t + 1 < TT) {       // fire x(t+1) LDGs first
                const float4* xp0 = reinterpret_cast<const float4*>(
                    &x[((size_t)(b16 + xs0) * TT + t + 1) * IN]);
                const float4* xp1 = reinterpret_cast<const float4*>(
                    &x[((size_t)(b16 + xs0 + 1) * TT + t + 1) * IN]);
                #pragma unroll
                for (int q = 0; q < 5; q++) { xv0[q] = xp0[q]; xv1[q] = xp1[q]; }
            }
            ull a3[4];
            if (is_w3m) {
                #pragma unroll
                for (int j = 0; j < 4; j++) a3[j] = b3;
                const float* wb3 = &sm[OFF_W + u3 * 4 + p3 * 2];
                const float* hb3 = A + q3 * 8;
                #pragma unroll
                for (int k = 0; k < KDIM; k++) {
                    ull wpp = *reinterpret_cast<const ull*>(wb3 + k * WROW);
                    const float* hr = hb3 + k * 32;
                    ulonglong2 hA = *reinterpret_cast<const ulonglong2*>(hr);
                    ulonglong2 hB = *reinterpret_cast<const ulonglong2*>(hr + 4);
                    a3[0] = fma2(wpp, hA.x, a3[0]);
                    a3[1] = fma2(wpp, hA.y, a3[1]);
                    a3[2] = fma2(wpp, hB.x, a3[2]);
                    a3[3] = fma2(wpp, hB.y, a3[3]);
                }
                // exchange gate-pairs between p=0 and p=1 lanes (xor 4 stays in 0..23)
                ull part[4];
                #pragma unroll
                for (int j = 0; j < 4; j++)
                    part[j] = __shfl_xor_sync(0x00FFFFFFu, a3[j], 4);
                if (p3 == 0) {
                    ull hd3[4];
                    #pragma unroll
                    for (int j = 0; j < 4; j++) {
                        float gi, gf, gg, go;
                        unpack2(a3[j],  gi, gf);
                        unpack2(part[j], gg, go);
                        float c = fsig(gf) * c1[j] + fsig(gi) * ftanh_(gg);
                        c1[j] = c;
                        hd3[j] = pack2(fsig(go) * ftanh_(c));
                    }
                    float* Bo = B + u3 * 32 + q3 * 8;
                    *reinterpret_cast<ulonglong2*>(Bo)     = make_ulonglong2(hd3[0], hd3[1]);
                    *reinterpret_cast<ulonglong2*>(Bo + 4) = make_ulonglong2(hd3[2], hd3[3]);
                }
            }
            if (is_l2 && t > 0) {
                // layer 2 on h(t-1) in A (dup layout: stride 2)
                float zi = 0.f, zf = 0.f, zg = 0.f, zo = 0.f;
                #pragma unroll
                for (int k = 0; k < HID; k++) {
                    float hvv = A[k * 32 + 2 * lane];
                    zi += sm[OFF_W2 +          k] * hvv;
                    zf += sm[OFF_W2 + HID    + k] * hvv;
                    zg += sm[OFF_W2 + 2*HID  + k] * hvv;
                    zo += sm[OFF_W2 + 3*HID  + k] * hvv;
                }
                float i2 = fsig  (zi + l2b[0] + l2w[0] * h2);
                float f2 = fsig  (zf + l2b[1] + l2w[1] * h2);
                float g2v= ftanh_(zg + l2b[2] + l2w[2] * h2);
                float o2 = fsig  (zo + l2b[3] + l2w[3] * h2);
                c2 = f2 * c2 + i2 * g2v;
                h2 = o2 * ftanh_(c2);
                sum_h2 += h2;
            }
            if (is_xp && t + 1 < TT) {       // store x(t+1) dup into B rows 51..70
                #pragma unroll
                for (int q = 0; q < 5; q++) {
                    #pragma unroll
                    for (int e = 0; e < 4; e++) {
                        float v0 = (e == 0) ? xv0[q].x : (e == 1) ? xv0[q].y : (e == 2) ? xv0[q].z : xv0[q].w;
                        float v1 = (e == 0) ? xv1[q].x : (e == 1) ? xv1[q].y : (e == 2) ? xv1[q].z : xv1[q].w;
                        int j = 4 * q + e;
                        *reinterpret_cast<ull*>(B + (HID + j) * 32 + 2 * xs0)       = pack2(v0);
                        *reinterpret_cast<ull*>(B + (HID + j) * 32 + 2 * (xs0 + 1)) = pack2(v1);
                    }
                }
            }
        }
        __syncthreads();
    }

    // ---------- final layer-2 step on h(T-1) + epilogue ----------
    if (is_l2) {
        const float* A = &sm[OFF_HX + (TT & 1) * HXBUF];
        float zi = 0.f, zf = 0.f, zg = 0.f, zo = 0.f;
        #pragma unroll
        for (int k = 0; k < HID; k++) {
            float hvv = A[k * 32 + 2 * lane];
            zi += sm[OFF_W2 +          k] * hvv;
            zf += sm[OFF_W2 + HID    + k] * hvv;
            zg += sm[OFF_W2 + 2*HID  + k] * hvv;
            zo += sm[OFF_W2 + 3*HID  + k] * hvv;
        }
        float i2 = fsig  (zi + l2b[0] + l2w[0] * h2);
        float f2 = fsig  (zf + l2b[1] + l2w[1] * h2);
        float g2v= ftanh_(zg + l2b[2] + l2w[2] * h2);
        float o2 = fsig  (zo + l2b[3] + l2w[3] * h2);
        c2 = f2 * c2 + i2 * g2v;
        h2 = o2 * ftanh_(c2);
        sum_h2 += h2;

        float agg = sum_h2 * (1.0f / TT);
        float mu  = W_mu[0] * agg + b_mu[0];
        float lv  = W_lv[0] * agg + b_lv[0];
        float sg  = __expf(0.5f * lv);
        int b = b16 + lane;
        out[b]           = mu - 1.96f * sg;
        out[BATCH + b]   = mu;
        out[2*BATCH + b] = mu + 1.96f * sg;
        out[3*BATCH + b] = lv;
    }
}

extern "C" void kernel_launch(void* const* d_in, const int* in_sizes, int n_in,
                              void* d_out, int out_size) {
    const float* x     = (const float*)d_in[0];
    const float* W_ih1 = (const float*)d_in[1];
    const float* W_hh1 = (const float*)d_in[2];
    const float* b_ih1 = (const float*)d_in[3];
    const float* b_hh1 = (const float*)d_in[4];
    const float* W_ih2 = (const float*)d_in[5];
    const float* W_hh2 = (const float*)d_in[6];
    const float* b_ih2 = (const float*)d_in[7];
    const float* b_hh2 = (const float*)d_in[8];
    const float* W_mu  = (const float*)d_in[9];
    const float* b_mu  = (const float*)d_in[10];
    const float* W_lv  = (const float*)d_in[11];
    const float* b_lv  = (const float*)d_in[12];
    float* out = (float*)d_out;

    cudaFuncSetAttribute(lstm_v9_kernel,
                         cudaFuncAttributeMaxDynamicSharedMemorySize, SMEM_BYTES);
    lstm_v9_kernel<<<NBLK, NTHR, SMEM_BYTES>>>(x, W_ih1, W_hh1, b_ih1, b_hh1,
                                               W_ih2, W_hh2, b_ih2, b_hh2,
                                               W_mu, b_mu, W_lv, b_lv, out);
}